// round 6
// baseline (speedup 1.0000x reference)
#include <cuda_runtime.h>
#include <cuda_fp16.h>
#include <math.h>
#include <stdint.h>

#define B_  32
#define N_  512
#define M_  512
#define D_  1024

// ---------------------------------------------------------------------------
// Scratch (__device__ globals — allocation-free rule)
// ---------------------------------------------------------------------------
__device__ __align__(256) float  g_S  [(size_t)B_ * N_ * M_];   // raw logits [n, m]
__device__ __align__(256) float  g_St [(size_t)B_ * N_ * M_];   // raw logits [m, n]
__device__ __align__(256) __half g_x1h[(size_t)B_ * N_ * D_], g_x1l[(size_t)B_ * N_ * D_];
__device__ __align__(256) __half g_x2h[(size_t)B_ * M_ * D_], g_x2l[(size_t)B_ * M_ * D_];

// ---------------------------------------------------------------------------
// helpers (plain sm_80+ features — valid on sm_103 non-'a' target)
// ---------------------------------------------------------------------------
__device__ __forceinline__ uint32_t smem_u32(const void* p) {
    uint32_t a;
    asm("{ .reg .u64 t; cvta.to.shared.u64 t, %1; cvt.u32.u64 %0, t; }" : "=r"(a) : "l"(p));
    return a;
}
__device__ __forceinline__ void cp16(uint32_t dst, const void* gsrc) {
    asm volatile("cp.async.cg.shared.global [%0], [%1], 16;" :: "r"(dst), "l"(gsrc) : "memory");
}
__device__ __forceinline__ void cp_commit() { asm volatile("cp.async.commit_group;" ::: "memory"); }
template <int NW> __device__ __forceinline__ void cp_wait() {
    asm volatile("cp.async.wait_group %0;" :: "n"(NW) : "memory");
}
__device__ __forceinline__ void ldsm4(uint32_t* r, uint32_t addr) {
    asm volatile("ldmatrix.sync.aligned.m8n8.x4.shared.b16 {%0,%1,%2,%3}, [%4];"
                 : "=r"(r[0]), "=r"(r[1]), "=r"(r[2]), "=r"(r[3]) : "r"(addr));
}
__device__ __forceinline__ void mma16816(float* c, const uint32_t* a, uint32_t b0, uint32_t b1) {
    asm volatile(
        "mma.sync.aligned.m16n8k16.row.col.f32.f16.f16.f32 "
        "{%0,%1,%2,%3}, {%4,%5,%6,%7}, {%8,%9}, {%0,%1,%2,%3};"
        : "+f"(c[0]), "+f"(c[1]), "+f"(c[2]), "+f"(c[3])
        : "r"(a[0]), "r"(a[1]), "r"(a[2]), "r"(a[3]), "r"(b0), "r"(b1));
}
__device__ __forceinline__ uint32_t tadr(uint32_t tbase, int row, int chunk) {
    return tbase + row * 64 + ((chunk ^ ((row >> 1) & 3)) << 4);
}

// ---------------------------------------------------------------------------
// HMMA GEMM (NT) + fused transpose epilogue.
// S[n, m] = sum_d (x1h+x1l)[n,d] * (x2h+x2l)[m,d];  St[m, n] = S[n, m]
// CTA 128x128, 8 warps (warp tile 64x32), K-step 32, 3-stage cp.async.
// ---------------------------------------------------------------------------
#define TILE_A_H 0
#define TILE_A_L 8192
#define TILE_B_H 16384
#define TILE_B_L 24576
#define STAGE_SZ 32768
#define NSTAGE   3
#define GEMM_SMEM (NSTAGE * STAGE_SZ)   // 98304; epilogue reuses as float[128][129] (66048 B)

__device__ __forceinline__ void load_stage(
    uint32_t sbase, int tid,
    const __half* __restrict__ Ahp, const __half* __restrict__ Alp,
    const __half* __restrict__ Bhp, const __half* __restrict__ Blp,
    int k0)
{
#pragma unroll
    for (int i = 0; i < 2; i++) {
        const int idx  = tid + i * 256;
        const int row  = idx >> 2;
        const int c    = idx & 3;
        const uint32_t sw = (uint32_t)(row * 64 + ((c ^ ((row >> 1) & 3)) << 4));
        const size_t g = (size_t)row * D_ + k0 + c * 8;
        cp16(sbase + TILE_A_H + sw, Ahp + g);
        cp16(sbase + TILE_A_L + sw, Alp + g);
        cp16(sbase + TILE_B_H + sw, Bhp + g);
        cp16(sbase + TILE_B_L + sw, Blp + g);
    }
    cp_commit();
}

__global__ __launch_bounds__(256, 2)
void gemm_hmma(const __half* __restrict__ Ah, const __half* __restrict__ Al,
               const __half* __restrict__ Bh, const __half* __restrict__ Bl,
               float* __restrict__ S, float* __restrict__ St)
{
    extern __shared__ __align__(128) char smem[];
    const uint32_t sb = smem_u32(smem);
    const int tid  = threadIdx.x;
    const int warp = tid >> 5;
    const int lane = tid & 31;
    const int b    = blockIdx.z;
    const int rA0  = blockIdx.y * 128;   // n
    const int rB0  = blockIdx.x * 128;   // m

    const __half* Ahp = Ah + (size_t)b * N_ * D_ + (size_t)rA0 * D_;
    const __half* Alp = Al + (size_t)b * N_ * D_ + (size_t)rA0 * D_;
    const __half* Bhp = Bh + (size_t)b * M_ * D_ + (size_t)rB0 * D_;
    const __half* Blp = Bl + (size_t)b * M_ * D_ + (size_t)rB0 * D_;

    const int warp_m = (warp >> 2) << 6;   // 0 or 64
    const int warp_n = (warp & 3) << 5;    // 0,32,64,96

    float acc[4][4][4];
#pragma unroll
    for (int i = 0; i < 4; i++)
#pragma unroll
        for (int j = 0; j < 4; j++)
#pragma unroll
            for (int q = 0; q < 4; q++) acc[i][j][q] = 0.f;

    const int arow = lane & 15;
    const int acx  = (lane >> 4) & 1;
    const int brow = (lane & 7) + ((lane & 16) >> 1);
    const int bcx  = (lane >> 3) & 1;

    const int T = D_ >> 5;   // 32
    load_stage(sb, tid, Ahp, Alp, Bhp, Blp, 0);
    load_stage(sb + STAGE_SZ, tid, Ahp, Alp, Bhp, Blp, 32);

    int stg = 0;
    for (int t = 0; t < T; t++) {
        if (t + 2 < T) cp_wait<1>(); else cp_wait<0>();
        __syncthreads();   // stage t resident + WAR cover for the prefetch below

        // prefetch t+2 FIRST so cp.async overlaps the whole compute step
        if (t + 2 < T) {
            int ps = stg + 2; if (ps >= NSTAGE) ps -= NSTAGE;
            load_stage(sb + (uint32_t)ps * STAGE_SZ, tid, Ahp, Alp, Bhp, Blp, (t + 2) << 5);
        }

        const uint32_t st = sb + (uint32_t)stg * STAGE_SZ;
#pragma unroll
        for (int kk = 0; kk < 2; kk++) {
            const int ac = kk * 2 + acx;
            const int bc = kk * 2 + bcx;
            // B fragments once per kk-half (16 regs live)
            uint32_t BH[2][4], BL[2][4];
#pragma unroll
            for (int j = 0; j < 2; j++) {
                ldsm4(BH[j], tadr(st + TILE_B_H, warp_n + j * 16 + brow, bc));
                ldsm4(BL[j], tadr(st + TILE_B_L, warp_n + j * 16 + brow, bc));
            }
            // per A-row: 2 ldsm + 12 mmas (small live set, latency hidden)
#pragma unroll
            for (int i = 0; i < 4; i++) {
                uint32_t AHr[4], ALr[4];
                ldsm4(AHr, tadr(st + TILE_A_H, warp_m + i * 16 + arow, ac));
                ldsm4(ALr, tadr(st + TILE_A_L, warp_m + i * 16 + arow, ac));
#pragma unroll
                for (int j = 0; j < 4; j++) {
                    const uint32_t bh0 = BH[j >> 1][(j & 1) * 2];
                    const uint32_t bh1 = BH[j >> 1][(j & 1) * 2 + 1];
                    const uint32_t bl0 = BL[j >> 1][(j & 1) * 2];
                    const uint32_t bl1 = BL[j >> 1][(j & 1) * 2 + 1];
                    mma16816(acc[i][j], AHr, bh0, bh1);   // hi*hi
                    mma16816(acc[i][j], AHr, bl0, bl1);   // hi*lo
                    mma16816(acc[i][j], ALr, bh0, bh1);   // lo*hi
                }
            }
        }
        if (++stg == NSTAGE) stg = 0;
    }

    // ---- epilogue: write S from regs; transpose via smem; write St ----
    float* Sb = S + (size_t)b * N_ * M_;
    const int tr = lane >> 2;
    const int tc = (lane & 3) * 2;

    __syncthreads();                       // all ldsm of last stage done -> smem reusable
    float* tile = reinterpret_cast<float*>(smem);   // [128][129]

#pragma unroll
    for (int i = 0; i < 4; i++) {
#pragma unroll
        for (int j = 0; j < 4; j++) {
            const int r = warp_m + i * 16 + tr;       // local n
            const int c = warp_n + j * 8 + tc;        // local m
            // global S (coalesced float2)
            *reinterpret_cast<float2*>(Sb + (size_t)(rA0 + r) * M_ + rB0 + c) =
                make_float2(acc[i][j][0], acc[i][j][1]);
            *reinterpret_cast<float2*>(Sb + (size_t)(rA0 + r + 8) * M_ + rB0 + c) =
                make_float2(acc[i][j][2], acc[i][j][3]);
            // smem tile for transpose
            tile[r * 129 + c]       = acc[i][j][0];
            tile[r * 129 + c + 1]   = acc[i][j][1];
            tile[(r + 8) * 129 + c]     = acc[i][j][2];
            tile[(r + 8) * 129 + c + 1] = acc[i][j][3];
        }
    }
    __syncthreads();

    float* Stb = St + (size_t)b * N_ * M_;
    const int mc   = tid & 127;        // local m (contiguous within warp -> conflict-free)
    const int half = tid >> 7;         // n half
#pragma unroll
    for (int i = 0; i < 16; i++) {
        const int n0 = half * 64 + i * 4;
        float4 v;
        v.x = tile[(n0 + 0) * 129 + mc];
        v.y = tile[(n0 + 1) * 129 + mc];
        v.z = tile[(n0 + 2) * 129 + mc];
        v.w = tile[(n0 + 3) * 129 + mc];
        *reinterpret_cast<float4*>(Stb + (size_t)(rB0 + mc) * N_ + rA0 + n0) = v;
    }
}

// ---------------------------------------------------------------------------
// fp32 -> fp16 hi/lo split, both inputs in one launch (grid.y selects input)
// ---------------------------------------------------------------------------
__global__ __launch_bounds__(256)
void split2(const float* __restrict__ x1, const float* __restrict__ x2,
            __half* __restrict__ x1h, __half* __restrict__ x1l,
            __half* __restrict__ x2h, __half* __restrict__ x2l, int n4)
{
    const float* x  = blockIdx.y ? x2  : x1;
    __half*      xh = blockIdx.y ? x2h : x1h;
    __half*      xl = blockIdx.y ? x2l : x1l;
    const int stride = gridDim.x * blockDim.x;
    for (int i = blockIdx.x * blockDim.x + threadIdx.x; i < n4; i += stride) {
        const float4 v = reinterpret_cast<const float4*>(x)[i];
        const __half h0 = __float2half_rn(v.x), h1 = __float2half_rn(v.y);
        const __half h2 = __float2half_rn(v.z), h3 = __float2half_rn(v.w);
        const __half l0 = __float2half_rn(v.x - __half2float(h0));
        const __half l1 = __float2half_rn(v.y - __half2float(h1));
        const __half l2 = __float2half_rn(v.z - __half2float(h2));
        const __half l3 = __float2half_rn(v.w - __half2float(h3));
        __half2* hp = reinterpret_cast<__half2*>(xh) + i * 2;
        __half2* lp = reinterpret_cast<__half2*>(xl) + i * 2;
        hp[0] = __halves2half2(h0, h1);  hp[1] = __halves2half2(h2, h3);
        lp[0] = __halves2half2(l0, l1);  lp[1] = __halves2half2(l2, l3);
    }
}

// ---------------------------------------------------------------------------
// Fused masked softmax + near-one-hot sparse apply; both directions in one
// launch (grid.y = 0: P12 @ x2, grid.y = 1: P21 @ x1).
// ---------------------------------------------------------------------------
#define TAU 1e-7f

__global__ __launch_bounds__(256)
void softmax_apply2(const float* __restrict__ S, const float* __restrict__ St,
                    const int* __restrict__ mask1, const int* __restrict__ mask2,
                    const float* __restrict__ x1, const float* __restrict__ x2,
                    float* __restrict__ out)
{
    __shared__ float se[512];
    __shared__ float sp[512];
    __shared__ int   sidx[512];
    __shared__ float red[8];
    __shared__ float bcast;
    __shared__ int   scnt;

    const int dir = blockIdx.y;
    const int row = blockIdx.x;          // 0 .. B*512-1
    const int b   = row >> 9;

    const float* Sr = (dir ? St : S) + (size_t)row * 512;
    const int*   mk = (dir ? mask1 : mask2) + (size_t)b * 512;
    const float* Xb = (dir ? x1 : x2) + (size_t)b * 512 * D_;
    float*       op = out + (size_t)dir * B_ * N_ * D_ + (size_t)row * D_;

    const int t    = threadIdx.x;
    const int lane = t & 31;
    const int warp = t >> 5;

    const int m0 = mk[t];
    const int m1 = mk[t + 256];
    const float v0 = m0 ? Sr[t]       : -INFINITY;
    const float v1 = m1 ? Sr[t + 256] : -INFINITY;

    float mx = fmaxf(v0, v1);
#pragma unroll
    for (int s = 16; s > 0; s >>= 1) mx = fmaxf(mx, __shfl_xor_sync(0xffffffffu, mx, s));
    if (lane == 0) red[warp] = mx;
    __syncthreads();
    if (t == 0) {
        float m = red[0];
#pragma unroll
        for (int k = 1; k < 8; k++) m = fmaxf(m, red[k]);
        bcast = m;
    }
    __syncthreads();
    mx = bcast;

    const float e0 = m0 ? __expf(v0 - mx) : 0.f;
    const float e1 = m1 ? __expf(v1 - mx) : 0.f;
    se[t] = e0;  se[t + 256] = e1;

    float sm = e0 + e1;
#pragma unroll
    for (int s = 16; s > 0; s >>= 1) sm += __shfl_xor_sync(0xffffffffu, sm, s);
    if (lane == 0) red[warp] = sm;
    __syncthreads();
    if (t == 0) {
        float s = red[0];
#pragma unroll
        for (int k = 1; k < 8; k++) s += red[k];
        bcast = 1.f / s;
    }
    __syncthreads();
    const float inv = bcast;

    if (t < 32) {
        int base = 0;
#pragma unroll
        for (int j = 0; j < 16; j++) {
            const float p = se[j * 32 + t] * inv;
            const bool sig = p > TAU;
            const unsigned bm = __ballot_sync(0xffffffffu, sig);
            if (sig) {
                const int pos = base + __popc(bm & ((1u << t) - 1u));
                sidx[pos] = j * 32 + t;
                sp[pos]   = p;
            }
            base += __popc(bm);
        }
        if (t == 0) scnt = base;
    }
    __syncthreads();

    const int cnt = scnt;
    float4 acc = make_float4(0.f, 0.f, 0.f, 0.f);
    for (int i = 0; i < cnt; i++) {
        const float p = sp[i];
        const float4 xv = *reinterpret_cast<const float4*>(Xb + (size_t)sidx[i] * D_ + t * 4);
        acc.x += p * xv.x;  acc.y += p * xv.y;
        acc.z += p * xv.z;  acc.w += p * xv.w;
    }
    *reinterpret_cast<float4*>(op + t * 4) = acc;
}

// ---------------------------------------------------------------------------
extern "C" void kernel_launch(void* const* d_in, const int* in_sizes, int n_in,
                              void* d_out, int out_size)
{
    const float* x1    = (const float*)d_in[0];
    const float* x2    = (const float*)d_in[1];
    const int*   mask1 = (const int*)  d_in[2];
    const int*   mask2 = (const int*)  d_in[3];

    float* out = (float*)d_out;

    float *S, *St;
    __half *x1h, *x1l, *x2h, *x2l;
    cudaGetSymbolAddress((void**)&S,   g_S);
    cudaGetSymbolAddress((void**)&St,  g_St);
    cudaGetSymbolAddress((void**)&x1h, g_x1h);  cudaGetSymbolAddress((void**)&x1l, g_x1l);
    cudaGetSymbolAddress((void**)&x2h, g_x2h);  cudaGetSymbolAddress((void**)&x2l, g_x2l);

    cudaFuncSetAttribute(gemm_hmma, cudaFuncAttributeMaxDynamicSharedMemorySize, GEMM_SMEM);

    // 1) fp16 hi/lo splits (both inputs, one launch)
    split2<<<dim3(1184, 2), 256>>>(x1, x2, x1h, x1l, x2h, x2l, B_ * N_ * D_ / 4);

    // 2) S = x1 @ x2^T  and  St = S^T  (fused epilogue)
    gemm_hmma<<<dim3(M_ / 128, N_ / 128, B_), 256, GEMM_SMEM>>>(
        x1h, x1l, x2h, x2l, S, St);

    // 3) fused masked-softmax + sparse apply, both directions, one launch
    softmax_apply2<<<dim3(B_ * N_, 2), 256>>>(S, St, mask1, mask2, x1, x2, out);
}

// round 7
// speedup vs baseline: 1.0511x; 1.0511x over previous
#include <cuda_runtime.h>
#include <cuda_fp16.h>
#include <math.h>
#include <stdint.h>

#define B_  32
#define N_  512
#define M_  512
#define D_  1024

// ---------------------------------------------------------------------------
// Scratch (__device__ globals — allocation-free rule)
// ---------------------------------------------------------------------------
__device__ __align__(256) float g_S [(size_t)B_ * N_ * M_];   // raw logits [n, m]
__device__ __align__(256) float g_St[(size_t)B_ * N_ * M_];   // raw logits [m, n]

// ---------------------------------------------------------------------------
// helpers (plain sm_80+ features — valid on sm_103 non-'a' target)
// ---------------------------------------------------------------------------
__device__ __forceinline__ uint32_t smem_u32(const void* p) {
    uint32_t a;
    asm("{ .reg .u64 t; cvta.to.shared.u64 t, %1; cvt.u32.u64 %0, t; }" : "=r"(a) : "l"(p));
    return a;
}
__device__ __forceinline__ void ldsm4(uint32_t* r, uint32_t addr) {
    asm volatile("ldmatrix.sync.aligned.m8n8.x4.shared.b16 {%0,%1,%2,%3}, [%4];"
                 : "=r"(r[0]), "=r"(r[1]), "=r"(r[2]), "=r"(r[3]) : "r"(addr));
}
__device__ __forceinline__ void mma16816(float* c, const uint32_t* a, uint32_t b0, uint32_t b1) {
    asm volatile(
        "mma.sync.aligned.m16n8k16.row.col.f32.f16.f16.f32 "
        "{%0,%1,%2,%3}, {%4,%5,%6,%7}, {%8,%9}, {%0,%1,%2,%3};"
        : "+f"(c[0]), "+f"(c[1]), "+f"(c[2]), "+f"(c[3])
        : "r"(a[0]), "r"(a[1]), "r"(a[2]), "r"(a[3]), "r"(b0), "r"(b1));
}

// 32B-row tile swizzle: conflict-free for both STS.128 and ldmatrix phases
__device__ __forceinline__ uint32_t sw16(int row, int c) {
    return (uint32_t)(row * 32 + ((c ^ ((row >> 2) & 1)) << 4));
}

// ---------------------------------------------------------------------------
// Fused fp32->fp16-split HMMA GEMM (NT) + transpose epilogue.
// S[n, m] = sum_d x1[n,d] * x2[m,d]  (fp32-grade via Markidis 3-mma split)
// St[m, n] = S[n, m]
// CTA 128x128, 8 warps (warp tile 64x32), K-step 16, 2-stage smem,
// in-kernel hi/lo conversion (register-staged LDG, no split pre-pass).
// ---------------------------------------------------------------------------
#define TILE_AH 0
#define TILE_AL 4096
#define TILE_BH 8192
#define TILE_BL 12288
#define STAGE_SZ 16384
#define EPI_SMEM (64 * 129 * 4)        // 33024
#define GEMM_SMEM (EPI_SMEM > 2 * STAGE_SZ ? EPI_SMEM : 2 * STAGE_SZ)

// convert 8 fp32 -> 8 fp16 hi + 8 fp16 lo (two uint4 stores worth)
__device__ __forceinline__ void cvt8(const float4 v0, const float4 v1,
                                     uint4& hi, uint4& lo)
{
    __half2 h0 = __floats2half2_rn(v0.x, v0.y);
    __half2 h1 = __floats2half2_rn(v0.z, v0.w);
    __half2 h2 = __floats2half2_rn(v1.x, v1.y);
    __half2 h3 = __floats2half2_rn(v1.z, v1.w);
    float2 f0 = __half22float2(h0), f1 = __half22float2(h1);
    float2 f2 = __half22float2(h2), f3 = __half22float2(h3);
    __half2 l0 = __floats2half2_rn(v0.x - f0.x, v0.y - f0.y);
    __half2 l1 = __floats2half2_rn(v0.z - f1.x, v0.w - f1.y);
    __half2 l2 = __floats2half2_rn(v1.x - f2.x, v1.y - f2.y);
    __half2 l3 = __floats2half2_rn(v1.z - f3.x, v1.w - f3.y);
    hi.x = *reinterpret_cast<uint32_t*>(&h0);  hi.y = *reinterpret_cast<uint32_t*>(&h1);
    hi.z = *reinterpret_cast<uint32_t*>(&h2);  hi.w = *reinterpret_cast<uint32_t*>(&h3);
    lo.x = *reinterpret_cast<uint32_t*>(&l0);  lo.y = *reinterpret_cast<uint32_t*>(&l1);
    lo.z = *reinterpret_cast<uint32_t*>(&l2);  lo.w = *reinterpret_cast<uint32_t*>(&l3);
}

__global__ __launch_bounds__(256, 2)
void gemm_fused(const float* __restrict__ X1, const float* __restrict__ X2,
                float* __restrict__ S, float* __restrict__ St)
{
    extern __shared__ __align__(128) char smem[];
    const uint32_t sb = smem_u32(smem);
    const int tid  = threadIdx.x;
    const int warp = tid >> 5;
    const int lane = tid & 31;
    const int b    = blockIdx.z;
    const int rA0  = blockIdx.y * 128;   // n
    const int rB0  = blockIdx.x * 128;   // m

    // ---- loader mapping: thread owns (row = tid>>1, 8-elem chunk c = tid&1) ----
    const int lrow = tid >> 1;
    const int lc   = tid & 1;
    const float* aptr = X1 + (size_t)b * N_ * D_ + (size_t)(rA0 + lrow) * D_ + lc * 8;
    const float* bptr = X2 + (size_t)b * M_ * D_ + (size_t)(rB0 + lrow) * D_ + lc * 8;
    const uint32_t swoff = sw16(lrow, lc);

    const int warp_m = (warp >> 2) << 6;   // 0 or 64
    const int warp_n = (warp & 3) << 5;    // 0,32,64,96

    float acc[4][4][4];
#pragma unroll
    for (int i = 0; i < 4; i++)
#pragma unroll
        for (int j = 0; j < 4; j++)
#pragma unroll
            for (int q = 0; q < 4; q++) acc[i][j][q] = 0.f;

    const int arow = lane & 15;
    const int acx  = (lane >> 4) & 1;
    const int brow = (lane & 7) + ((lane & 16) >> 1);
    const int bcx  = (lane >> 3) & 1;

    const int T = D_ >> 4;   // 64 K-steps of 16

    // ---- prologue: load + convert stage 0 ----
    float4 a0 = *reinterpret_cast<const float4*>(aptr);
    float4 a1 = *reinterpret_cast<const float4*>(aptr + 4);
    float4 b0 = *reinterpret_cast<const float4*>(bptr);
    float4 b1 = *reinterpret_cast<const float4*>(bptr + 4);
    {
        uint4 hi, lo;
        cvt8(a0, a1, hi, lo);
        *reinterpret_cast<uint4*>(smem + TILE_AH + swoff) = hi;
        *reinterpret_cast<uint4*>(smem + TILE_AL + swoff) = lo;
        cvt8(b0, b1, hi, lo);
        *reinterpret_cast<uint4*>(smem + TILE_BH + swoff) = hi;
        *reinterpret_cast<uint4*>(smem + TILE_BL + swoff) = lo;
    }

    for (int t = 0; t < T; t++) {
        __syncthreads();   // stage t&1 visible; prior reads of stage (t+1)&1 done

        const bool pf = (t + 1 < T);
        if (pf) {          // LDG for stage t+1 (latency hidden under the mma block)
            const int k0 = (t + 1) << 4;
            a0 = *reinterpret_cast<const float4*>(aptr + k0);
            a1 = *reinterpret_cast<const float4*>(aptr + k0 + 4);
            b0 = *reinterpret_cast<const float4*>(bptr + k0);
            b1 = *reinterpret_cast<const float4*>(bptr + k0 + 4);
        }

        // ---- mma on stage t&1 ----
        const uint32_t st = sb + (uint32_t)(t & 1) * STAGE_SZ;
        uint32_t BH[2][4], BL[2][4];
#pragma unroll
        for (int j = 0; j < 2; j++) {
            ldsm4(BH[j], st + TILE_BH + sw16(warp_n + j * 16 + brow, bcx));
            ldsm4(BL[j], st + TILE_BL + sw16(warp_n + j * 16 + brow, bcx));
        }
#pragma unroll
        for (int i = 0; i < 4; i++) {
            uint32_t AHr[4], ALr[4];
            ldsm4(AHr, st + TILE_AH + sw16(warp_m + i * 16 + arow, acx));
            ldsm4(ALr, st + TILE_AL + sw16(warp_m + i * 16 + arow, acx));
#pragma unroll
            for (int j = 0; j < 4; j++) {
                const uint32_t bh0 = BH[j >> 1][(j & 1) * 2];
                const uint32_t bh1 = BH[j >> 1][(j & 1) * 2 + 1];
                const uint32_t bl0 = BL[j >> 1][(j & 1) * 2];
                const uint32_t bl1 = BL[j >> 1][(j & 1) * 2 + 1];
                mma16816(acc[i][j], AHr, bh0, bh1);   // hi*hi
                mma16816(acc[i][j], AHr, bl0, bl1);   // hi*lo
                mma16816(acc[i][j], ALr, bh0, bh1);   // lo*hi
            }
        }

        // ---- convert + STS stage t+1 into the other buffer ----
        if (pf) {
            char* dst = smem + ((t + 1) & 1) * STAGE_SZ;
            uint4 hi, lo;
            cvt8(a0, a1, hi, lo);
            *reinterpret_cast<uint4*>(dst + TILE_AH + swoff) = hi;
            *reinterpret_cast<uint4*>(dst + TILE_AL + swoff) = lo;
            cvt8(b0, b1, hi, lo);
            *reinterpret_cast<uint4*>(dst + TILE_BH + swoff) = hi;
            *reinterpret_cast<uint4*>(dst + TILE_BL + swoff) = lo;
        }
    }

    // ---- epilogue: write S from regs; transpose via 64x129 smem; write St ----
    float* Sb = S + (size_t)b * N_ * M_;
    const int tr = lane >> 2;
    const int tc = (lane & 3) * 2;
#pragma unroll
    for (int i = 0; i < 4; i++) {
#pragma unroll
        for (int j = 0; j < 4; j++) {
            const int r = warp_m + i * 16 + tr;
            const int c = warp_n + j * 8 + tc;
            *reinterpret_cast<float2*>(Sb + (size_t)(rA0 + r) * M_ + rB0 + c) =
                make_float2(acc[i][j][0], acc[i][j][1]);
            *reinterpret_cast<float2*>(Sb + (size_t)(rA0 + r + 8) * M_ + rB0 + c) =
                make_float2(acc[i][j][2], acc[i][j][3]);
        }
    }

    float* epi = reinterpret_cast<float*>(smem);   // [64][129]
    float* Stb = St + (size_t)b * N_ * M_;
    const int mc = tid & 127;
    const int q  = tid >> 7;
#pragma unroll
    for (int p = 0; p < 2; p++) {
        __syncthreads();   // p=0: last-stage ldsm done; p=1: prior pass reads done
        if ((warp >> 2) == p) {
#pragma unroll
            for (int i = 0; i < 4; i++)
#pragma unroll
                for (int j = 0; j < 4; j++) {
                    const int r = i * 16 + tr;            // local row within 64
                    const int c = warp_n + j * 8 + tc;
                    epi[r * 129 + c]           = acc[i][j][0];
                    epi[r * 129 + c + 1]       = acc[i][j][1];
                    epi[(r + 8) * 129 + c]     = acc[i][j][2];
                    epi[(r + 8) * 129 + c + 1] = acc[i][j][3];
                }
        }
        __syncthreads();
#pragma unroll
        for (int i = 0; i < 8; i++) {
            const int n0 = q * 32 + i * 4;
            float4 v;
            v.x = epi[(n0 + 0) * 129 + mc];
            v.y = epi[(n0 + 1) * 129 + mc];
            v.z = epi[(n0 + 2) * 129 + mc];
            v.w = epi[(n0 + 3) * 129 + mc];
            *reinterpret_cast<float4*>(Stb + (size_t)(rB0 + mc) * N_ + rA0 + p * 64 + n0) = v;
        }
    }
}

// ---------------------------------------------------------------------------
// Fused masked softmax + near-one-hot sparse apply; both directions in one
// launch (grid.y = 0: P12 @ x2, grid.y = 1: P21 @ x1).
// ---------------------------------------------------------------------------
#define TAU 1e-7f

__global__ __launch_bounds__(256)
void softmax_apply2(const float* __restrict__ S, const float* __restrict__ St,
                    const int* __restrict__ mask1, const int* __restrict__ mask2,
                    const float* __restrict__ x1, const float* __restrict__ x2,
                    float* __restrict__ out)
{
    __shared__ float se[512];
    __shared__ float sp[512];
    __shared__ int   sidx[512];
    __shared__ float red[8];
    __shared__ float bcast;
    __shared__ int   scnt;

    const int dir = blockIdx.y;
    const int row = blockIdx.x;          // 0 .. B*512-1
    const int b   = row >> 9;

    const float* Sr = (dir ? St : S) + (size_t)row * 512;
    const int*   mk = (dir ? mask1 : mask2) + (size_t)b * 512;
    const float* Xb = (dir ? x1 : x2) + (size_t)b * 512 * D_;
    float*       op = out + (size_t)dir * B_ * N_ * D_ + (size_t)row * D_;

    const int t    = threadIdx.x;
    const int lane = t & 31;
    const int warp = t >> 5;

    const int m0 = mk[t];
    const int m1 = mk[t + 256];
    const float v0 = m0 ? Sr[t]       : -INFINITY;
    const float v1 = m1 ? Sr[t + 256] : -INFINITY;

    float mx = fmaxf(v0, v1);
#pragma unroll
    for (int s = 16; s > 0; s >>= 1) mx = fmaxf(mx, __shfl_xor_sync(0xffffffffu, mx, s));
    if (lane == 0) red[warp] = mx;
    __syncthreads();
    if (t == 0) {
        float m = red[0];
#pragma unroll
        for (int k = 1; k < 8; k++) m = fmaxf(m, red[k]);
        bcast = m;
    }
    __syncthreads();
    mx = bcast;

    const float e0 = m0 ? __expf(v0 - mx) : 0.f;
    const float e1 = m1 ? __expf(v1 - mx) : 0.f;
    se[t] = e0;  se[t + 256] = e1;

    float sm = e0 + e1;
#pragma unroll
    for (int s = 16; s > 0; s >>= 1) sm += __shfl_xor_sync(0xffffffffu, sm, s);
    if (lane == 0) red[warp] = sm;
    __syncthreads();
    if (t == 0) {
        float s = red[0];
#pragma unroll
        for (int k = 1; k < 8; k++) s += red[k];
        bcast = 1.f / s;
    }
    __syncthreads();
    const float inv = bcast;

    if (t < 32) {
        int base = 0;
#pragma unroll
        for (int j = 0; j < 16; j++) {
            const float p = se[j * 32 + t] * inv;
            const bool sig = p > TAU;
            const unsigned bm = __ballot_sync(0xffffffffu, sig);
            if (sig) {
                const int pos = base + __popc(bm & ((1u << t) - 1u));
                sidx[pos] = j * 32 + t;
                sp[pos]   = p;
            }
            base += __popc(bm);
        }
        if (t == 0) scnt = base;
    }
    __syncthreads();

    const int cnt = scnt;
    float4 acc = make_float4(0.f, 0.f, 0.f, 0.f);
    for (int i = 0; i < cnt; i++) {
        const float p = sp[i];
        const float4 xv = *reinterpret_cast<const float4*>(Xb + (size_t)sidx[i] * D_ + t * 4);
        acc.x += p * xv.x;  acc.y += p * xv.y;
        acc.z += p * xv.z;  acc.w += p * xv.w;
    }
    *reinterpret_cast<float4*>(op + t * 4) = acc;
}

// ---------------------------------------------------------------------------
extern "C" void kernel_launch(void* const* d_in, const int* in_sizes, int n_in,
                              void* d_out, int out_size)
{
    const float* x1    = (const float*)d_in[0];
    const float* x2    = (const float*)d_in[1];
    const int*   mask1 = (const int*)  d_in[2];
    const int*   mask2 = (const int*)  d_in[3];

    float* out = (float*)d_out;

    float *S, *St;
    cudaGetSymbolAddress((void**)&S,  g_S);
    cudaGetSymbolAddress((void**)&St, g_St);

    cudaFuncSetAttribute(gemm_fused, cudaFuncAttributeMaxDynamicSharedMemorySize, GEMM_SMEM);

    // 1) S = x1 @ x2^T and St = S^T (in-kernel fp16 hi/lo split, fused transpose)
    gemm_fused<<<dim3(M_ / 128, N_ / 128, B_), 256, GEMM_SMEM>>>(x1, x2, S, St);

    // 2) fused masked-softmax + near-one-hot sparse apply, both directions
    softmax_apply2<<<dim3(B_ * N_, 2), 256>>>(S, St, mask1, mask2, x1, x2, out);
}

// round 8
// speedup vs baseline: 1.3213x; 1.2571x over previous
#include <cuda_runtime.h>
#include <cuda_fp16.h>
#include <math.h>
#include <stdint.h>

#define B_  32
#define N_  512
#define M_  512
#define D_  1024

// ---------------------------------------------------------------------------
// Scratch (__device__ globals — allocation-free rule)
// ---------------------------------------------------------------------------
__device__ __align__(256) float g_S [(size_t)B_ * N_ * M_];   // raw logits [n, m]
__device__ __align__(256) float g_St[(size_t)B_ * N_ * M_];   // raw logits [m, n]

// ---------------------------------------------------------------------------
// helpers (plain sm_80+ features — valid on sm_103 non-'a' target)
// ---------------------------------------------------------------------------
__device__ __forceinline__ uint32_t smem_u32(const void* p) {
    uint32_t a;
    asm("{ .reg .u64 t; cvta.to.shared.u64 t, %1; cvt.u32.u64 %0, t; }" : "=r"(a) : "l"(p));
    return a;
}
__device__ __forceinline__ void ldsm4(uint32_t* r, uint32_t addr) {
    asm volatile("ldmatrix.sync.aligned.m8n8.x4.shared.b16 {%0,%1,%2,%3}, [%4];"
                 : "=r"(r[0]), "=r"(r[1]), "=r"(r[2]), "=r"(r[3]) : "r"(addr));
}
__device__ __forceinline__ void mma16816(float* c, const uint32_t* a, uint32_t b0, uint32_t b1) {
    asm volatile(
        "mma.sync.aligned.m16n8k16.row.col.f32.f16.f16.f32 "
        "{%0,%1,%2,%3}, {%4,%5,%6,%7}, {%8,%9}, {%0,%1,%2,%3};"
        : "+f"(c[0]), "+f"(c[1]), "+f"(c[2]), "+f"(c[3])
        : "r"(a[0]), "r"(a[1]), "r"(a[2]), "r"(a[3]), "r"(b0), "r"(b1));
}

// 32B-row tile swizzle: conflict-free for both STS.128 and ldmatrix phases
__device__ __forceinline__ uint32_t sw16(int row, int c) {
    return (uint32_t)(row * 32 + ((c ^ ((row >> 2) & 1)) << 4));
}

// ---------------------------------------------------------------------------
// Fused fp32->fp16-split HMMA GEMM (NT) + transpose epilogue (unchanged R7).
// ---------------------------------------------------------------------------
#define TILE_AH 0
#define TILE_AL 4096
#define TILE_BH 8192
#define TILE_BL 12288
#define STAGE_SZ 16384
#define EPI_SMEM (64 * 129 * 4)
#define GEMM_SMEM (EPI_SMEM > 2 * STAGE_SZ ? EPI_SMEM : 2 * STAGE_SZ)

__device__ __forceinline__ void cvt8(const float4 v0, const float4 v1,
                                     uint4& hi, uint4& lo)
{
    __half2 h0 = __floats2half2_rn(v0.x, v0.y);
    __half2 h1 = __floats2half2_rn(v0.z, v0.w);
    __half2 h2 = __floats2half2_rn(v1.x, v1.y);
    __half2 h3 = __floats2half2_rn(v1.z, v1.w);
    float2 f0 = __half22float2(h0), f1 = __half22float2(h1);
    float2 f2 = __half22float2(h2), f3 = __half22float2(h3);
    __half2 l0 = __floats2half2_rn(v0.x - f0.x, v0.y - f0.y);
    __half2 l1 = __floats2half2_rn(v0.z - f1.x, v0.w - f1.y);
    __half2 l2 = __floats2half2_rn(v1.x - f2.x, v1.y - f2.y);
    __half2 l3 = __floats2half2_rn(v1.z - f3.x, v1.w - f3.y);
    hi.x = *reinterpret_cast<uint32_t*>(&h0);  hi.y = *reinterpret_cast<uint32_t*>(&h1);
    hi.z = *reinterpret_cast<uint32_t*>(&h2);  hi.w = *reinterpret_cast<uint32_t*>(&h3);
    lo.x = *reinterpret_cast<uint32_t*>(&l0);  lo.y = *reinterpret_cast<uint32_t*>(&l1);
    lo.z = *reinterpret_cast<uint32_t*>(&l2);  lo.w = *reinterpret_cast<uint32_t*>(&l3);
}

__global__ __launch_bounds__(256, 2)
void gemm_fused(const float* __restrict__ X1, const float* __restrict__ X2,
                float* __restrict__ S, float* __restrict__ St)
{
    extern __shared__ __align__(128) char smem[];
    const uint32_t sb = smem_u32(smem);
    const int tid  = threadIdx.x;
    const int warp = tid >> 5;
    const int lane = tid & 31;
    const int b    = blockIdx.z;
    const int rA0  = blockIdx.y * 128;   // n
    const int rB0  = blockIdx.x * 128;   // m

    const int lrow = tid >> 1;
    const int lc   = tid & 1;
    const float* aptr = X1 + (size_t)b * N_ * D_ + (size_t)(rA0 + lrow) * D_ + lc * 8;
    const float* bptr = X2 + (size_t)b * M_ * D_ + (size_t)(rB0 + lrow) * D_ + lc * 8;
    const uint32_t swoff = sw16(lrow, lc);

    const int warp_m = (warp >> 2) << 6;
    const int warp_n = (warp & 3) << 5;

    float acc[4][4][4];
#pragma unroll
    for (int i = 0; i < 4; i++)
#pragma unroll
        for (int j = 0; j < 4; j++)
#pragma unroll
            for (int q = 0; q < 4; q++) acc[i][j][q] = 0.f;

    const int arow = lane & 15;
    const int acx  = (lane >> 4) & 1;
    const int brow = (lane & 7) + ((lane & 16) >> 1);
    const int bcx  = (lane >> 3) & 1;

    const int T = D_ >> 4;   // 64

    float4 a0 = *reinterpret_cast<const float4*>(aptr);
    float4 a1 = *reinterpret_cast<const float4*>(aptr + 4);
    float4 b0 = *reinterpret_cast<const float4*>(bptr);
    float4 b1 = *reinterpret_cast<const float4*>(bptr + 4);
    {
        uint4 hi, lo;
        cvt8(a0, a1, hi, lo);
        *reinterpret_cast<uint4*>(smem + TILE_AH + swoff) = hi;
        *reinterpret_cast<uint4*>(smem + TILE_AL + swoff) = lo;
        cvt8(b0, b1, hi, lo);
        *reinterpret_cast<uint4*>(smem + TILE_BH + swoff) = hi;
        *reinterpret_cast<uint4*>(smem + TILE_BL + swoff) = lo;
    }

    for (int t = 0; t < T; t++) {
        __syncthreads();

        const bool pf = (t + 1 < T);
        if (pf) {
            const int k0 = (t + 1) << 4;
            a0 = *reinterpret_cast<const float4*>(aptr + k0);
            a1 = *reinterpret_cast<const float4*>(aptr + k0 + 4);
            b0 = *reinterpret_cast<const float4*>(bptr + k0);
            b1 = *reinterpret_cast<const float4*>(bptr + k0 + 4);
        }

        const uint32_t st = sb + (uint32_t)(t & 1) * STAGE_SZ;
        uint32_t BH[2][4], BL[2][4];
#pragma unroll
        for (int j = 0; j < 2; j++) {
            ldsm4(BH[j], st + TILE_BH + sw16(warp_n + j * 16 + brow, bcx));
            ldsm4(BL[j], st + TILE_BL + sw16(warp_n + j * 16 + brow, bcx));
        }
#pragma unroll
        for (int i = 0; i < 4; i++) {
            uint32_t AHr[4], ALr[4];
            ldsm4(AHr, st + TILE_AH + sw16(warp_m + i * 16 + arow, acx));
            ldsm4(ALr, st + TILE_AL + sw16(warp_m + i * 16 + arow, acx));
#pragma unroll
            for (int j = 0; j < 4; j++) {
                const uint32_t bh0 = BH[j >> 1][(j & 1) * 2];
                const uint32_t bh1 = BH[j >> 1][(j & 1) * 2 + 1];
                const uint32_t bl0 = BL[j >> 1][(j & 1) * 2];
                const uint32_t bl1 = BL[j >> 1][(j & 1) * 2 + 1];
                mma16816(acc[i][j], AHr, bh0, bh1);
                mma16816(acc[i][j], AHr, bl0, bl1);
                mma16816(acc[i][j], ALr, bh0, bh1);
            }
        }

        if (pf) {
            char* dst = smem + ((t + 1) & 1) * STAGE_SZ;
            uint4 hi, lo;
            cvt8(a0, a1, hi, lo);
            *reinterpret_cast<uint4*>(dst + TILE_AH + swoff) = hi;
            *reinterpret_cast<uint4*>(dst + TILE_AL + swoff) = lo;
            cvt8(b0, b1, hi, lo);
            *reinterpret_cast<uint4*>(dst + TILE_BH + swoff) = hi;
            *reinterpret_cast<uint4*>(dst + TILE_BL + swoff) = lo;
        }
    }

    float* Sb = S + (size_t)b * N_ * M_;
    const int tr = lane >> 2;
    const int tc = (lane & 3) * 2;
#pragma unroll
    for (int i = 0; i < 4; i++) {
#pragma unroll
        for (int j = 0; j < 4; j++) {
            const int r = warp_m + i * 16 + tr;
            const int c = warp_n + j * 8 + tc;
            *reinterpret_cast<float2*>(Sb + (size_t)(rA0 + r) * M_ + rB0 + c) =
                make_float2(acc[i][j][0], acc[i][j][1]);
            *reinterpret_cast<float2*>(Sb + (size_t)(rA0 + r + 8) * M_ + rB0 + c) =
                make_float2(acc[i][j][2], acc[i][j][3]);
        }
    }

    float* epi = reinterpret_cast<float*>(smem);   // [64][129]
    float* Stb = St + (size_t)b * N_ * M_;
    const int mc = tid & 127;
    const int q  = tid >> 7;
#pragma unroll
    for (int p = 0; p < 2; p++) {
        __syncthreads();
        if ((warp >> 2) == p) {
#pragma unroll
            for (int i = 0; i < 4; i++)
#pragma unroll
                for (int j = 0; j < 4; j++) {
                    const int r = i * 16 + tr;
                    const int c = warp_n + j * 8 + tc;
                    epi[r * 129 + c]           = acc[i][j][0];
                    epi[r * 129 + c + 1]       = acc[i][j][1];
                    epi[(r + 8) * 129 + c]     = acc[i][j][2];
                    epi[(r + 8) * 129 + c + 1] = acc[i][j][3];
                }
        }
        __syncthreads();
#pragma unroll
        for (int i = 0; i < 8; i++) {
            const int n0 = q * 32 + i * 4;
            float4 v;
            v.x = epi[(n0 + 0) * 129 + mc];
            v.y = epi[(n0 + 1) * 129 + mc];
            v.z = epi[(n0 + 2) * 129 + mc];
            v.w = epi[(n0 + 3) * 129 + mc];
            *reinterpret_cast<float4*>(Stb + (size_t)(rB0 + mc) * N_ + rA0 + p * 64 + n0) = v;
        }
    }
}

// ---------------------------------------------------------------------------
// Warp-per-row fused masked softmax + near-one-hot sparse apply.
// 8 rows per block (one per warp), zero block barriers, warp-synchronous.
// grid = (B*512/8, 2); dir 0: P12 @ x2 -> out[0..], dir 1: P21 @ x1 -> out[..].
// ---------------------------------------------------------------------------
#define TAU 1e-7f
#define LCAP 512     // worst-case significant entries per row (correctness bound)

__global__ __launch_bounds__(256)
void softmax_apply3(const float* __restrict__ S, const float* __restrict__ St,
                    const int* __restrict__ mask1, const int* __restrict__ mask2,
                    const float* __restrict__ x1, const float* __restrict__ x2,
                    float* __restrict__ out)
{
    __shared__ float sp  [8][LCAP];
    __shared__ int   sidx[8][LCAP];

    const int dir  = blockIdx.y;
    const int warp = threadIdx.x >> 5;
    const int lane = threadIdx.x & 31;
    const int row  = blockIdx.x * 8 + warp;      // 0 .. B*512-1
    const int b    = row >> 9;

    const float* Sr = (dir ? St : S) + (size_t)row * 512;
    const int*   mk = (dir ? mask1 : mask2) + (size_t)b * 512;
    const float* Xb = (dir ? x1 : x2) + (size_t)b * 512 * D_;
    float*       op = out + (size_t)dir * B_ * N_ * D_ + (size_t)row * D_;

    // ---- load 16 logits/lane + mask, fold mask, find max ----
    const float4* Sr4 = reinterpret_cast<const float4*>(Sr);
    const int4*   mk4 = reinterpret_cast<const int4*>(mk);
    float v[16];
    float mx = -INFINITY;
#pragma unroll
    for (int i = 0; i < 4; i++) {
        const float4 f = Sr4[i * 32 + lane];
        const int4   m = mk4[i * 32 + lane];
        v[i * 4 + 0] = m.x ? f.x : -INFINITY;
        v[i * 4 + 1] = m.y ? f.y : -INFINITY;
        v[i * 4 + 2] = m.z ? f.z : -INFINITY;
        v[i * 4 + 3] = m.w ? f.w : -INFINITY;
        mx = fmaxf(mx, fmaxf(fmaxf(v[i*4], v[i*4+1]), fmaxf(v[i*4+2], v[i*4+3])));
    }
#pragma unroll
    for (int s = 16; s > 0; s >>= 1) mx = fmaxf(mx, __shfl_xor_sync(0xffffffffu, mx, s));

    // ---- exp + sum ----
    float sum = 0.f;
#pragma unroll
    for (int i = 0; i < 16; i++) {
        const float e = (v[i] == -INFINITY) ? 0.f : __expf(v[i] - mx);
        v[i] = e;
        sum += e;
    }
#pragma unroll
    for (int s = 16; s > 0; s >>= 1) sum += __shfl_xor_sync(0xffffffffu, sum, s);
    const float inv = 1.f / sum;

    // ---- per-warp deterministic significant list (ballot prefix) ----
    int cnt = 0;
#pragma unroll
    for (int j = 0; j < 16; j++) {
        const int i = j >> 2, c = j & 3;               // element idx = i*128 + lane*4 + c
        const float p = v[i * 4 + c] * inv;
        const bool sig = p > TAU;
        const unsigned bm = __ballot_sync(0xffffffffu, sig);
        if (sig) {
            const int pos = cnt + __popc(bm & ((1u << lane) - 1u));
            sidx[warp][pos] = i * 128 + lane * 4 + c;
            sp[warp][pos]   = p;
        }
        cnt += __popc(bm);
    }
    __syncwarp();

    // ---- gather-accumulate: out[row,:] = sum_i p_i * X[k_i,:] ----
    float4 A[8];
#pragma unroll
    for (int u = 0; u < 8; u++) A[u] = make_float4(0.f, 0.f, 0.f, 0.f);

    const float4* Xb4 = reinterpret_cast<const float4*>(Xb);
    for (int i = 0; i < cnt; i++) {
        const float p = sp[warp][i];
        const int   k = sidx[warp][i];
        const float4* xr = Xb4 + (size_t)k * (D_ / 4);
#pragma unroll
        for (int u = 0; u < 8; u++) {
            const float4 xv = xr[u * 32 + lane];
            A[u].x += p * xv.x;  A[u].y += p * xv.y;
            A[u].z += p * xv.z;  A[u].w += p * xv.w;
        }
    }

    float4* op4 = reinterpret_cast<float4*>(op);
#pragma unroll
    for (int u = 0; u < 8; u++) op4[u * 32 + lane] = A[u];
}

// ---------------------------------------------------------------------------
extern "C" void kernel_launch(void* const* d_in, const int* in_sizes, int n_in,
                              void* d_out, int out_size)
{
    const float* x1    = (const float*)d_in[0];
    const float* x2    = (const float*)d_in[1];
    const int*   mask1 = (const int*)  d_in[2];
    const int*   mask2 = (const int*)  d_in[3];

    float* out = (float*)d_out;

    float *S, *St;
    cudaGetSymbolAddress((void**)&S,  g_S);
    cudaGetSymbolAddress((void**)&St, g_St);

    cudaFuncSetAttribute(gemm_fused, cudaFuncAttributeMaxDynamicSharedMemorySize, GEMM_SMEM);

    // 1) S = x1 @ x2^T and St = S^T (in-kernel fp16 hi/lo split, fused transpose)
    gemm_fused<<<dim3(M_ / 128, N_ / 128, B_), 256, GEMM_SMEM>>>(x1, x2, S, St);

    // 2) warp-per-row fused masked-softmax + sparse apply, both directions
    softmax_apply3<<<dim3(B_ * N_ / 8, 2), 256>>>(S, St, mask1, mask2, x1, x2, out);
}